// round 11
// baseline (speedup 1.0000x reference)
#include <cuda_runtime.h>

// LSTM scan: T=2048, B=2048, IN=5, H=10.
// R6: chain + L1tex-queue attack (R2/R5 both pinned at ~380 cyc/step).
//  - no __syncwarp (converged warp, program-ordered smem).
//  - x loads distributed: lanes 0-14 load ONE float/step into a register
//    ring; values broadcast via SHFL at the END of the previous step
//    (off-chain). 5 LDG/step -> 1; the step now STARTS with the critical
//    h LDS (nothing queued ahead of it in L1tex).
//  - i/f/o weights+bias prescaled by 0.5: sigmoid = fma(.5,tanh(z'),.5).
//  - 2-warp blocks, smem h double-buffer (5 LDS.64), PF=8, peeled tail.

#define T_STEPS 2048
#define BATCH   2048
#define IN_DIM  5
#define HID     10
#define BPW     3                               // batches per warp (30 lanes)
#define WARPS   2
#define NTHREADS (WARPS * 32)                   // 64
#define BPB     (WARPS * BPW)                   // 6 batches per block
#define NBLOCKS ((BATCH + BPB - 1) / BPB)       // 342
#define PF      8                               // x ring depth (divides T)
#define XSTRIDE (BATCH * IN_DIM)                // floats per timestep

typedef unsigned long long u64;

__device__ __forceinline__ u64 pack2(float lo, float hi) {
    u64 r;
    asm("mov.b64 %0, {%1, %2};" : "=l"(r) : "f"(lo), "f"(hi));
    return r;
}
__device__ __forceinline__ void unpack2(u64 v, float& lo, float& hi) {
    asm("mov.b64 {%0, %1}, %2;" : "=f"(lo), "=f"(hi) : "l"(v));
}
__device__ __forceinline__ u64 ffma2(u64 a, u64 b, u64 c) {
    u64 d;
    asm("fma.rn.f32x2 %0, %1, %2, %3;" : "=l"(d) : "l"(a), "l"(b), "l"(c));
    return d;
}
__device__ __forceinline__ float tanha(float z) {
    float r;
    asm("tanh.approx.f32 %0, %1;" : "=f"(r) : "f"(z));
    return r;
}
// weights already prescaled by 0.5 for sigmoid gates:
__device__ __forceinline__ float fsig_pre(float zh) {   // zh = 0.5*z
    return fmaf(0.5f, tanha(zh), 0.5f);
}

// One LSTM step.
//  - v0..v2 hold this step's x pairs (pre-shuffled at end of previous step).
//  - DOPF: refill ring[d] with x(t+PF) (loader lanes only).
//  - ends by pre-shuffling next step's x from ring[(d+1)&7].
#define STEP_BODY(d, DOPF) do {                                               \
    const int par_ = (d) & 1;                                                 \
    /* chain head: h of previous step (STS below, same warp, program order)*/ \
    const u64 hp0 = rp[par_][0], hp1 = rp[par_][1], hp2 = rp[par_][2];        \
    const u64 hp3 = rp[par_][3], hp4 = rp[par_][4];                           \
    if (DOPF) {                       /* off-chain refill, 1 LDG, 15 lanes */ \
        if (ldr) { ring[d] = __ldg(xpf); xpf += XSTRIDE; }                    \
    }                                                                         \
    float gate[4];                                                            \
    _Pragma("unroll")                                                         \
    for (int q = 0; q < 4; q++) {                                             \
        u64 acc = pack2(bias[q], 0.0f);  /* x-part retires during LDS wait */ \
        acc = ffma2(wp[q][0], v0, acc);                                       \
        acc = ffma2(wp[q][1], v1, acc);                                       \
        acc = ffma2(wp[q][2], v2, acc);                                       \
        acc = ffma2(wp[q][3], hp0, acc);                                      \
        acc = ffma2(wp[q][4], hp1, acc);                                      \
        acc = ffma2(wp[q][5], hp2, acc);                                      \
        acc = ffma2(wp[q][6], hp3, acc);                                      \
        acc = ffma2(wp[q][7], hp4, acc);                                      \
        float lo_, hi_; unpack2(acc, lo_, hi_);                               \
        gate[q] = lo_ + hi_;                                                  \
    }                                                                         \
    const float is = fsig_pre(gate[0]);                                       \
    const float fs = fsig_pre(gate[1]);                                       \
    const float gt = tanha(gate[2]);                                          \
    const float os = fsig_pre(gate[3]);                                       \
    c = fs * c + is * gt;                                                     \
    const float hn = os * tanha(c);                                           \
    wq[par_ ^ 1][0] = hn;             /* STS into next buffer */              \
    if (active) *op = hn;                                                     \
    op += ostep;                                                              \
    /* pre-shuffle next step's x (off the recurrent chain) */                 \
    {                                                                         \
        const float rv = ring[((d) + 1) & (PF - 1)];                          \
        const float s0 = __shfl_sync(0xFFFFFFFFu, rv, g5 + 0);                \
        const float s1 = __shfl_sync(0xFFFFFFFFu, rv, g5 + 1);                \
        const float s2 = __shfl_sync(0xFFFFFFFFu, rv, g5 + 2);                \
        const float s3 = __shfl_sync(0xFFFFFFFFu, rv, g5 + 3);                \
        const float s4 = __shfl_sync(0xFFFFFFFFu, rv, g5 + 4);                \
        v0 = pack2(s0, s1); v1 = pack2(s2, s3); v2 = pack2(s4, 0.0f);         \
    }                                                                         \
} while (0)

__global__ void __launch_bounds__(NTHREADS, 1) lstm_scan_kernel(
    const float* __restrict__ x,     // [T, B, IN]
    const float* __restrict__ hx0,   // [B, H]
    const float* __restrict__ cx0,   // [B, H]
    const float* __restrict__ Wih,   // [4H, IN]
    const float* __restrict__ Whh,   // [4H, H]
    const float* __restrict__ bih,   // [4H]
    const float* __restrict__ bhh,   // [4H]
    float* __restrict__ out)         // [T*B, H]
{
    // Double-buffered h, per warp. Group rows of 10 floats -> 5 LDS.64
    // broadcasts per group, disjoint banks across groups: conflict-free.
    __shared__ __align__(16) float hbuf[2][WARPS][32];

    const int lane = threadIdx.x & 31;
    const int warp = threadIdx.x >> 5;
    const int g    = lane / HID;          // batch slot in warp (0..3)
    const int h    = lane % HID;          // hidden unit 0..9
    const int g5   = (g < BPW ? g : BPW - 1) * IN_DIM;  // shfl src base

    const int  b_raw  = blockIdx.x * BPB + warp * BPW + g;
    const bool active = (g < BPW) && (b_raw < BATCH);
    const int  b      = active ? b_raw : (BATCH - 1);   // clamp: safe loads

    // Loader lanes: lane 0..14 covers 3 batches x 5 floats of x per step.
    const bool ldr = (lane < BPW * IN_DIM);
    const int  gl  = ldr ? lane / IN_DIM : 0;            // loader's batch slot
    const int  kk  = ldr ? lane % IN_DIM : 0;            // loader's x index
    const int  bl  = blockIdx.x * BPB + warp * BPW + gl; // always < BATCH

    // Pack weights, v-layout [x0..x4, 0, h0..h9] (8 f32x2 per gate).
    // Gates i,f,o (q != 2) prescaled by 0.5 -> sigmoid needs no pre-mul.
    u64 wp[4][8];
    float bias[4];
#pragma unroll
    for (int q = 0; q < 4; q++) {
        const float sc = (q == 2) ? 1.0f : 0.5f;
        const int r = q * HID + h;
        float wv[16];
#pragma unroll
        for (int k = 0; k < IN_DIM; k++) wv[k] = sc * Wih[r * IN_DIM + k];
        wv[5] = 0.0f;                                    // pad slot
#pragma unroll
        for (int j = 0; j < HID; j++) wv[6 + j] = sc * Whh[r * HID + j];
#pragma unroll
        for (int p = 0; p < 8; p++) wp[q][p] = pack2(wv[2 * p], wv[2 * p + 1]);
        bias[q] = sc * (bih[r] + bhh[r]);
    }

    float c = cx0[(size_t)b * HID + h];

    // h exchange pointers. Inactive lanes write words 30/31 (never read).
    const int gr = (g < BPW ? g : BPW - 1) * HID;
    const u64* rp[2] = { (const u64*)&hbuf[0][warp][gr],
                         (const u64*)&hbuf[1][warp][gr] };
    float* wq[2] = { &hbuf[0][warp][g * HID + h],
                     &hbuf[1][warp][g * HID + h] };
    wq[0][0] = hx0[(size_t)b * HID + h];   // initial h into buffer 0

    // x register ring: loader lanes hold one float per slot.
    float ring[PF];
#pragma unroll
    for (int d = 0; d < PF; d++) ring[d] = 0.0f;
    const float* xpf = x + (size_t)bl * IN_DIM + kk;
    if (ldr) {
#pragma unroll
        for (int d = 0; d < PF; d++) {
            ring[d] = __ldg(xpf);
            xpf += XSTRIDE;
        }
    }
    // xpf now points at x(t=PF) for loader lanes.

    // Pre-shuffle step 0's x.
    u64 v0, v1, v2;
    {
        const float rv = ring[0];
        const float s0 = __shfl_sync(0xFFFFFFFFu, rv, g5 + 0);
        const float s1 = __shfl_sync(0xFFFFFFFFu, rv, g5 + 1);
        const float s2 = __shfl_sync(0xFFFFFFFFu, rv, g5 + 2);
        const float s3 = __shfl_sync(0xFFFFFFFFu, rv, g5 + 3);
        const float s4 = __shfl_sync(0xFFFFFFFFu, rv, g5 + 4);
        v0 = pack2(s0, s1); v1 = pack2(s2, s3); v2 = pack2(s4, 0.0f);
    }

    const size_t ostep = (size_t)BATCH * HID;
    float* op = out + (size_t)b * HID + h;

    // Main loop: all chunks except the last refill the ring.
#pragma unroll 1
    for (int tc = 0; tc < T_STEPS - PF; tc += PF) {
#pragma unroll
        for (int d = 0; d < PF; d++) STEP_BODY(d, true);
    }
    // Peeled final chunk: consume the ring, no refills.
#pragma unroll
    for (int d = 0; d < PF; d++) STEP_BODY(d, false);
}

extern "C" void kernel_launch(void* const* d_in, const int* in_sizes, int n_in,
                              void* d_out, int out_size) {
    (void)in_sizes; (void)n_in; (void)out_size;
    const float* x   = (const float*)d_in[0];
    const float* hx0 = (const float*)d_in[1];
    const float* cx0 = (const float*)d_in[2];
    const float* Wih = (const float*)d_in[3];
    const float* Whh = (const float*)d_in[4];
    const float* bih = (const float*)d_in[5];
    const float* bhh = (const float*)d_in[6];
    float* out = (float*)d_out;

    lstm_scan_kernel<<<NBLOCKS, NTHREADS>>>(x, hx0, cx0, Wih, Whh, bih, bhh, out);
}

// round 12
// speedup vs baseline: 1.0902x; 1.0902x over previous
#include <cuda_runtime.h>

// LSTM scan: T=2048, B=2048, IN=5, H=10.
// R7 = R5 base (best: 408us) + isolated chain micro-cuts:
//  - 3+2 split h-dot with fadd2 combine (shorter hp-paced chain)
//  - i/f/o weights+bias prescaled by 0.5 (sigmoid needs no pre-mul)
//  - pre-packed bias u64 constants; STS(hn) issued before the STG
//  - PF=4 (body fits the 6KB L0 I$; PF=4 proved sufficient in R2)
// Kept from R5: 2-warp blocks (342), smem h double-buffer + __syncwarp,
// per-lane 5-LDG x register ring, MUFU.TANH activations, f32x2 gate math.

#define T_STEPS 2048
#define BATCH   2048
#define IN_DIM  5
#define HID     10
#define BPW     3                               // batches per warp (30 lanes)
#define WARPS   2
#define NTHREADS (WARPS * 32)                   // 64
#define BPB     (WARPS * BPW)                   // 6 batches per block
#define NBLOCKS ((BATCH + BPB - 1) / BPB)       // 342
#define PF      4                               // x prefetch depth (divides T)

typedef unsigned long long u64;

__device__ __forceinline__ u64 pack2(float lo, float hi) {
    u64 r;
    asm("mov.b64 %0, {%1, %2};" : "=l"(r) : "f"(lo), "f"(hi));
    return r;
}
__device__ __forceinline__ void unpack2(u64 v, float& lo, float& hi) {
    asm("mov.b64 {%0, %1}, %2;" : "=f"(lo), "=f"(hi) : "l"(v));
}
__device__ __forceinline__ u64 ffma2(u64 a, u64 b, u64 c) {
    u64 d;
    asm("fma.rn.f32x2 %0, %1, %2, %3;" : "=l"(d) : "l"(a), "l"(b), "l"(c));
    return d;
}
__device__ __forceinline__ u64 fmul2(u64 a, u64 b) {
    u64 d;
    asm("mul.rn.f32x2 %0, %1, %2;" : "=l"(d) : "l"(a), "l"(b));
    return d;
}
__device__ __forceinline__ u64 fadd2(u64 a, u64 b) {
    u64 d;
    asm("add.rn.f32x2 %0, %1, %2;" : "=l"(d) : "l"(a), "l"(b));
    return d;
}
__device__ __forceinline__ float tanha(float z) {
    float r;
    asm("tanh.approx.f32 %0, %1;" : "=f"(r) : "f"(z));
    return r;
}
// weights already prescaled by 0.5 for sigmoid gates:
__device__ __forceinline__ float fsig_pre(float zh) {   // zh = 0.5*z
    return fmaf(0.5f, tanha(zh), 0.5f);
}

// One LSTM step. DOPF: issue the x prefetch for PF steps ahead.
// par = d&1 selects the h double-buffer (compile-time after unroll).
#define STEP_BODY(d, DOPF) do {                                               \
    const int par_ = (d) & 1;                                                 \
    float nx0, nx1, nx2, nx3, nx4;                                            \
    if (DOPF) {                       /* compile-time constant */             \
        nx0 = __ldg(xpf + 0); nx1 = __ldg(xpf + 1); nx2 = __ldg(xpf + 2);     \
        nx3 = __ldg(xpf + 3); nx4 = __ldg(xpf + 4);                           \
        xpf += xstep;                                                         \
    }                                                                         \
    __syncwarp();                     /* prev step's h writes -> visible */   \
    const u64 hp0 = rp[par_][0], hp1 = rp[par_][1], hp2 = rp[par_][2];        \
    const u64 hp3 = rp[par_][3], hp4 = rp[par_][4];                           \
    const u64 v0 = pack2(xr[d][0], xr[d][1]);                                 \
    const u64 v1 = pack2(xr[d][2], xr[d][3]);                                 \
    const u64 v2 = pack2(xr[d][4], 0.0f);                                     \
    float gate[4];                                                            \
    _Pragma("unroll")                                                         \
    for (int q = 0; q < 4; q++) {                                             \
        u64 accA = biasp[q];          /* x-part retires during LDS wait */    \
        accA = ffma2(wp[q][0], v0, accA);                                     \
        accA = ffma2(wp[q][1], v1, accA);                                     \
        accA = ffma2(wp[q][2], v2, accA);                                     \
        accA = ffma2(wp[q][3], hp0, accA);                                    \
        accA = ffma2(wp[q][4], hp1, accA);                                    \
        accA = ffma2(wp[q][5], hp2, accA);                                    \
        u64 accB = fmul2(wp[q][6], hp3);   /* parallel 2-chain */             \
        accB = ffma2(wp[q][7], hp4, accB);                                    \
        const u64 acc = fadd2(accA, accB);                                    \
        float lo_, hi_; unpack2(acc, lo_, hi_);                               \
        gate[q] = lo_ + hi_;                                                  \
    }                                                                         \
    const float is = fsig_pre(gate[0]);                                       \
    const float fs = fsig_pre(gate[1]);                                       \
    const float gt = tanha(gate[2]);                                          \
    const float os = fsig_pre(gate[3]);                                       \
    c = fs * c + is * gt;                                                     \
    const float hn = os * tanha(c);                                           \
    wq[par_ ^ 1][0] = hn;             /* STS first: feeds next step's chain */\
    if (active) *op = hn;             /* STG after: fire-and-forget */        \
    op += ostep;                                                              \
    if (DOPF) {                                                               \
        xr[d][0] = nx0; xr[d][1] = nx1; xr[d][2] = nx2;                       \
        xr[d][3] = nx3; xr[d][4] = nx4;                                       \
    }                                                                         \
} while (0)

__global__ void __launch_bounds__(NTHREADS, 1) lstm_scan_kernel(
    const float* __restrict__ x,     // [T, B, IN]
    const float* __restrict__ hx0,   // [B, H]
    const float* __restrict__ cx0,   // [B, H]
    const float* __restrict__ Wih,   // [4H, IN]
    const float* __restrict__ Whh,   // [4H, H]
    const float* __restrict__ bih,   // [4H]
    const float* __restrict__ bhh,   // [4H]
    float* __restrict__ out)         // [T*B, H]
{
    // Double-buffered h, per warp. Group rows of 10 floats -> 5 LDS.64
    // broadcasts per group, disjoint banks across groups: conflict-free.
    __shared__ __align__(16) float hbuf[2][WARPS][32];

    const int lane = threadIdx.x & 31;
    const int warp = threadIdx.x >> 5;
    const int g    = lane / HID;          // batch slot in warp (0..3)
    const int h    = lane % HID;          // hidden unit 0..9

    const int  b_raw  = blockIdx.x * BPB + warp * BPW + g;
    const bool active = (g < BPW) && (b_raw < BATCH);
    const int  b      = active ? b_raw : (BATCH - 1);   // clamp: safe loads

    // Pack weights, v-layout [x0..x4, 0, h0..h9] (8 f32x2 per gate).
    // Gates i,f,o (q != 2) prescaled by 0.5 -> sigmoid needs no pre-mul.
    u64 wp[4][8];
    u64 biasp[4];
#pragma unroll
    for (int q = 0; q < 4; q++) {
        const float sc = (q == 2) ? 1.0f : 0.5f;
        const int r = q * HID + h;
        float wv[16];
#pragma unroll
        for (int k = 0; k < IN_DIM; k++) wv[k] = sc * Wih[r * IN_DIM + k];
        wv[5] = 0.0f;                                    // pad slot
#pragma unroll
        for (int j = 0; j < HID; j++) wv[6 + j] = sc * Whh[r * HID + j];
#pragma unroll
        for (int p = 0; p < 8; p++) wp[q][p] = pack2(wv[2 * p], wv[2 * p + 1]);
        biasp[q] = pack2(sc * (bih[r] + bhh[r]), 0.0f);
    }

    float c = cx0[(size_t)b * HID + h];

    // h exchange pointers. Inactive lanes write words 30/31 (never read).
    const int gr = (g < BPW ? g : BPW - 1) * HID;
    const u64* rp[2] = { (const u64*)&hbuf[0][warp][gr],
                         (const u64*)&hbuf[1][warp][gr] };
    float* wq[2] = { &hbuf[0][warp][g * HID + h],
                     &hbuf[1][warp][g * HID + h] };
    wq[0][0] = hx0[(size_t)b * HID + h];   // initial h into buffer 0

    // Preload x rows 0..PF-1 into the register ring.
    float xr[PF][IN_DIM];
#pragma unroll
    for (int d = 0; d < PF; d++) {
        const float* pp = x + ((size_t)d * BATCH + b) * IN_DIM;
#pragma unroll
        for (int k = 0; k < IN_DIM; k++) xr[d][k] = __ldg(pp + k);
    }

    const size_t xstep = (size_t)BATCH * IN_DIM;
    const size_t ostep = (size_t)BATCH * HID;
    const float* xpf = x + ((size_t)PF * BATCH + b) * IN_DIM;   // next fetch
    float* op = out + (size_t)b * HID + h;

    // Main loop: all chunks except the last prefetch unconditionally.
#pragma unroll 1
    for (int tc = 0; tc < T_STEPS - PF; tc += PF) {
#pragma unroll
        for (int d = 0; d < PF; d++) STEP_BODY(d, true);
    }
    // Peeled final chunk: consume the ring, no prefetch, no branches.
#pragma unroll
    for (int d = 0; d < PF; d++) STEP_BODY(d, false);
}

extern "C" void kernel_launch(void* const* d_in, const int* in_sizes, int n_in,
                              void* d_out, int out_size) {
    (void)in_sizes; (void)n_in; (void)out_size;
    const float* x   = (const float*)d_in[0];
    const float* hx0 = (const float*)d_in[1];
    const float* cx0 = (const float*)d_in[2];
    const float* Wih = (const float*)d_in[3];
    const float* Whh = (const float*)d_in[4];
    const float* bih = (const float*)d_in[5];
    const float* bhh = (const float*)d_in[6];
    float* out = (float*)d_out;

    lstm_scan_kernel<<<NBLOCKS, NTHREADS>>>(x, hx0, cx0, Wih, Whh, bih, bhh, out);
}

// round 13
// speedup vs baseline: 1.1872x; 1.0890x over previous
#include <cuda_runtime.h>

// LSTM scan: T=2048, B=2048, IN=5, H=10.
// R8 = R7 (397us) + exchange-turnaround cuts:
//  - NO __syncwarp in the step: converged warp, per-warp program-ordered
//    smem (R6 empirically validated correctness of sync-free hand-off).
//  - h reload widened to 2x LDS.128 + 1x LDS.64 via 64B-padded group rows
//    (3 LSU ops instead of 5 ahead of the chain-critical first pair).
// Kept from R7: PF=4 raw-x ring, prescaled i/f/o weights (sigmoid without
// pre-mul), 3+2 split h-dot with fadd2 combine, pre-packed bias, STS before
// STG, 2-warp blocks (342), MUFU.TANH activations, f32x2 gate math.

#define T_STEPS 2048
#define BATCH   2048
#define IN_DIM  5
#define HID     10
#define BPW     3                               // batches per warp (30 lanes)
#define WARPS   2
#define NTHREADS (WARPS * 32)                   // 64
#define BPB     (WARPS * BPW)                   // 6 batches per block
#define NBLOCKS ((BATCH + BPB - 1) / BPB)       // 342
#define PF      4                               // x prefetch depth (divides T)

typedef unsigned long long u64;

__device__ __forceinline__ u64 pack2(float lo, float hi) {
    u64 r;
    asm("mov.b64 %0, {%1, %2};" : "=l"(r) : "f"(lo), "f"(hi));
    return r;
}
__device__ __forceinline__ void unpack2(u64 v, float& lo, float& hi) {
    asm("mov.b64 {%0, %1}, %2;" : "=f"(lo), "=f"(hi) : "l"(v));
}
__device__ __forceinline__ u64 ffma2(u64 a, u64 b, u64 c) {
    u64 d;
    asm("fma.rn.f32x2 %0, %1, %2, %3;" : "=l"(d) : "l"(a), "l"(b), "l"(c));
    return d;
}
__device__ __forceinline__ u64 fmul2(u64 a, u64 b) {
    u64 d;
    asm("mul.rn.f32x2 %0, %1, %2;" : "=l"(d) : "l"(a), "l"(b));
    return d;
}
__device__ __forceinline__ u64 fadd2(u64 a, u64 b) {
    u64 d;
    asm("add.rn.f32x2 %0, %1, %2;" : "=l"(d) : "l"(a), "l"(b));
    return d;
}
__device__ __forceinline__ float tanha(float z) {
    float r;
    asm("tanh.approx.f32 %0, %1;" : "=f"(r) : "f"(z));
    return r;
}
// weights already prescaled by 0.5 for sigmoid gates:
__device__ __forceinline__ float fsig_pre(float zh) {   // zh = 0.5*z
    return fmaf(0.5f, tanha(zh), 0.5f);
}

// One LSTM step. DOPF: issue the x prefetch for PF steps ahead.
// par = d&1 selects the h double-buffer (compile-time after unroll).
// No syncwarp: converged warp; STS(t) -> LDS(t+1) is per-warp program-
// ordered through the LSU, and the compiler must preserve may-alias order.
#define STEP_BODY(d, DOPF) do {                                               \
    const int par_ = (d) & 1;                                                 \
    float nx0, nx1, nx2, nx3, nx4;                                            \
    if (DOPF) {                       /* compile-time constant */             \
        nx0 = __ldg(xpf + 0); nx1 = __ldg(xpf + 1); nx2 = __ldg(xpf + 2);     \
        nx3 = __ldg(xpf + 3); nx4 = __ldg(xpf + 4);                           \
        xpf += xstep;                                                         \
    }                                                                         \
    /* chain head: previous step's h, 2x LDS.128 + 1x LDS.64 */               \
    const float4 hA = *rpA[par_];                                             \
    const float4 hB = *rpB[par_];                                             \
    const float2 hC = *rpC[par_];                                             \
    const u64 hp0 = pack2(hA.x, hA.y), hp1 = pack2(hA.z, hA.w);               \
    const u64 hp2 = pack2(hB.x, hB.y), hp3 = pack2(hB.z, hB.w);               \
    const u64 hp4 = pack2(hC.x, hC.y);                                        \
    const u64 v0 = pack2(xr[d][0], xr[d][1]);                                 \
    const u64 v1 = pack2(xr[d][2], xr[d][3]);                                 \
    const u64 v2 = pack2(xr[d][4], 0.0f);                                     \
    float gate[4];                                                            \
    _Pragma("unroll")                                                         \
    for (int q = 0; q < 4; q++) {                                             \
        u64 accA = biasp[q];          /* x-part retires during LDS wait */    \
        accA = ffma2(wp[q][0], v0, accA);                                     \
        accA = ffma2(wp[q][1], v1, accA);                                     \
        accA = ffma2(wp[q][2], v2, accA);                                     \
        accA = ffma2(wp[q][3], hp0, accA);                                    \
        accA = ffma2(wp[q][4], hp1, accA);                                    \
        accA = ffma2(wp[q][5], hp2, accA);                                    \
        u64 accB = fmul2(wp[q][6], hp3);   /* parallel 2-chain */             \
        accB = ffma2(wp[q][7], hp4, accB);                                    \
        const u64 acc = fadd2(accA, accB);                                    \
        float lo_, hi_; unpack2(acc, lo_, hi_);                               \
        gate[q] = lo_ + hi_;                                                  \
    }                                                                         \
    const float is = fsig_pre(gate[0]);                                       \
    const float fs = fsig_pre(gate[1]);                                       \
    const float gt = tanha(gate[2]);                                          \
    const float os = fsig_pre(gate[3]);                                       \
    c = fs * c + is * gt;                                                     \
    const float hn = os * tanha(c);                                           \
    wq[par_ ^ 1][0] = hn;             /* STS first: feeds next step's chain */\
    if (active) *op = hn;             /* STG after: fire-and-forget */        \
    op += ostep;                                                              \
    if (DOPF) {                                                               \
        xr[d][0] = nx0; xr[d][1] = nx1; xr[d][2] = nx2;                       \
        xr[d][3] = nx3; xr[d][4] = nx4;                                       \
    }                                                                         \
} while (0)

__global__ void __launch_bounds__(NTHREADS, 1) lstm_scan_kernel(
    const float* __restrict__ x,     // [T, B, IN]
    const float* __restrict__ hx0,   // [B, H]
    const float* __restrict__ cx0,   // [B, H]
    const float* __restrict__ Wih,   // [4H, IN]
    const float* __restrict__ Whh,   // [4H, H]
    const float* __restrict__ bih,   // [4H]
    const float* __restrict__ bhh,   // [4H]
    float* __restrict__ out)         // [T*B, H]
{
    // Double-buffered h, per warp. Group rows padded to 16 floats (64B):
    // rows are 16B-aligned -> LDS.128 legal. Row 3 = scratch for the two
    // inactive lanes (written, never read). Within a group all lanes read
    // the same 16B line (broadcast); groups hit disjoint lines: no
    // conflicts.
    __shared__ __align__(16) float hbuf[2][WARPS][4][16];

    const int lane = threadIdx.x & 31;
    const int warp = threadIdx.x >> 5;
    const int g    = lane / HID;          // batch slot in warp (0..3)
    const int h    = lane % HID;          // hidden unit 0..9

    const int  b_raw  = blockIdx.x * BPB + warp * BPW + g;
    const bool active = (g < BPW) && (b_raw < BATCH);
    const int  b      = active ? b_raw : (BATCH - 1);   // clamp: safe loads

    // Pack weights, v-layout [x0..x4, 0, h0..h9] (8 f32x2 per gate).
    // Gates i,f,o (q != 2) prescaled by 0.5 -> sigmoid needs no pre-mul.
    u64 wp[4][8];
    u64 biasp[4];
#pragma unroll
    for (int q = 0; q < 4; q++) {
        const float sc = (q == 2) ? 1.0f : 0.5f;
        const int r = q * HID + h;
        float wv[16];
#pragma unroll
        for (int k = 0; k < IN_DIM; k++) wv[k] = sc * Wih[r * IN_DIM + k];
        wv[5] = 0.0f;                                    // pad slot
#pragma unroll
        for (int j = 0; j < HID; j++) wv[6 + j] = sc * Whh[r * HID + j];
#pragma unroll
        for (int p = 0; p < 8; p++) wp[q][p] = pack2(wv[2 * p], wv[2 * p + 1]);
        biasp[q] = pack2(sc * (bih[r] + bhh[r]), 0.0f);
    }

    float c = cx0[(size_t)b * HID + h];

    // h exchange pointers (computed once). Reads use the group row clamped
    // to a valid group; inactive lanes write into scratch row 3.
    const int gr = (g < BPW) ? g : (BPW - 1);
    const float4* rpA[2] = { (const float4*)&hbuf[0][warp][gr][0],
                             (const float4*)&hbuf[1][warp][gr][0] };
    const float4* rpB[2] = { (const float4*)&hbuf[0][warp][gr][4],
                             (const float4*)&hbuf[1][warp][gr][4] };
    const float2* rpC[2] = { (const float2*)&hbuf[0][warp][gr][8],
                             (const float2*)&hbuf[1][warp][gr][8] };
    float* wq[2] = { &hbuf[0][warp][g][h],
                     &hbuf[1][warp][g][h] };
    wq[0][0] = hx0[(size_t)b * HID + h];   // initial h into buffer 0
    __syncwarp();                          // one-time: order init vs step 0

    // Preload x rows 0..PF-1 into the register ring.
    float xr[PF][IN_DIM];
#pragma unroll
    for (int d = 0; d < PF; d++) {
        const float* pp = x + ((size_t)d * BATCH + b) * IN_DIM;
#pragma unroll
        for (int k = 0; k < IN_DIM; k++) xr[d][k] = __ldg(pp + k);
    }

    const size_t xstep = (size_t)BATCH * IN_DIM;
    const size_t ostep = (size_t)BATCH * HID;
    const float* xpf = x + ((size_t)PF * BATCH + b) * IN_DIM;   // next fetch
    float* op = out + (size_t)b * HID + h;

    // Main loop: all chunks except the last prefetch unconditionally.
#pragma unroll 1
    for (int tc = 0; tc < T_STEPS - PF; tc += PF) {
#pragma unroll
        for (int d = 0; d < PF; d++) STEP_BODY(d, true);
    }
    // Peeled final chunk: consume the ring, no prefetch, no branches.
#pragma unroll
    for (int d = 0; d < PF; d++) STEP_BODY(d, false);
}

extern "C" void kernel_launch(void* const* d_in, const int* in_sizes, int n_in,
                              void* d_out, int out_size) {
    (void)in_sizes; (void)n_in; (void)out_size;
    const float* x   = (const float*)d_in[0];
    const float* hx0 = (const float*)d_in[1];
    const float* cx0 = (const float*)d_in[2];
    const float* Wih = (const float*)d_in[3];
    const float* Whh = (const float*)d_in[4];
    const float* bih = (const float*)d_in[5];
    const float* bhh = (const float*)d_in[6];
    float* out = (float*)d_out;

    lstm_scan_kernel<<<NBLOCKS, NTHREADS>>>(x, hx0, cx0, Wih, Whh, bih, bhh, out);
}